// round 7
// baseline (speedup 1.0000x reference)
#include <cuda_runtime.h>
#include <cuda_bf16.h>

// BSplineLoss on GB300 (sm_103a).
// Layout: seq[B][64][3] f32, col0 = knots (strictly increasing), col1..2 = coeffs.
// Reference math:
//   kf = [0,0,0,0, knots...]            (68 entries)
//   low = kf[3] = 0, high = kf[64] = knots[60]
//   t_i = (i/19) * knots[60],  i = 0..19
//   j   = #{ knots[0..59] <= t }        (searchsorted(inner, t, 'right') folded:
//          inner = [0, knots[0..59]], s = cnt+1 + DEGREE-1, idx = s-3+k = j+k)
//   control points v[j..j+3] (homogeneous, w = 1), cubic De Boor, 3 levels.
// loss = sum over (B,20,2) of (pred-true)^2 / (B*20)

static constexpr int B_ROWS       = 65536;
static constexpr int ROWS_PER_BLK = 16;
static constexpr int THREADS      = ROWS_PER_BLK * 20;   // 320
static constexpr int NUM_BLOCKS   = B_ROWS / ROWS_PER_BLK; // 4096
static constexpr int TEN_STRIDE   = 196;                 // padded (f4-aligned)
static constexpr int ROW_STRIDE   = 2 * TEN_STRIDE;      // 392 floats; %32 == 8 -> bank shift/row
static constexpr float INV_COUNT  = 1.0f / (65536.0f * 20.0f);

// Block partials (allocation-free scratch per harness rules).
__device__ float g_partial[NUM_BLOCKS];

__device__ __forceinline__ void eval_spline(const float* __restrict__ s, int i,
                                            float& ox, float& oy) {
    const float high = s[180];                 // knots[60]
    const float t = (float)i * (1.0f / 19.0f) * high;

    // j = count of knots[0..59] <= t   (binary search, 6 iterations)
    int lo = 0, hi = 60;
    while (lo < hi) {
        int mid = (lo + hi) >> 1;
        bool le = (s[mid * 3] <= t);
        lo = le ? (mid + 1) : lo;
        hi = le ? hi : mid;
    }
    const int j = lo;                          // 0..60

    float px[4], py[4], pw[4];
#pragma unroll
    for (int k = 0; k < 4; ++k) {
        int c = (j + k) * 3;
        px[k] = s[c + 1];
        py[k] = s[c + 2];
        pw[k] = 1.0f;
    }

#pragma unroll
    for (int l = 1; l <= 3; ++l) {
#pragma unroll
        for (int k = 3; k >= 1; --k) {
            if (k < l) break;
            const int ik = j + k;
            // kf[m] = (m<4) ? 0 : knots[m-4]
            const float ki = (ik < 4) ? 0.0f : s[(ik - 4) * 3];
            const float kj = s[(ik - l) * 3];   // kf[ik+4-l]; k>=l so index >= 0
            const float denom = kj - ki;
            const float a = (denom != 0.0f) ? __fdividef(t - ki, denom) : 0.0f;
            const float b = 1.0f - a;
            px[k] = b * px[k - 1] + a * px[k];
            py[k] = b * py[k - 1] + a * py[k];
            pw[k] = b * pw[k - 1] + a * pw[k];
        }
    }
    const float rw = __fdividef(1.0f, pw[3]);
    ox = px[3] * rw;
    oy = py[3] * rw;
}

__global__ __launch_bounds__(THREADS)
void bspline_loss_kernel(const float* __restrict__ pred,
                         const float* __restrict__ truth) {
    __shared__ __align__(16) float sh[ROWS_PER_BLK * ROW_STRIDE];
    __shared__ float wsum[THREADS / 32];

    const int rowBase = blockIdx.x * ROWS_PER_BLK;

    // Cooperative float4 staging: 16 rows x 2 tensors x 48 float4 each
    {
        const float4* gp = (const float4*)(pred)  + (size_t)rowBase * 48;
        const float4* gt = (const float4*)(truth) + (size_t)rowBase * 48;
        float4* s4 = (float4*)sh;  // row r at f4 offset r*98, tensor t at +t*49
        for (int idx = threadIdx.x; idx < ROWS_PER_BLK * 2 * 48; idx += THREADS) {
            int r    = idx / 96;
            int rem  = idx - r * 96;
            int tens = rem / 48;
            int k    = rem - tens * 48;
            float4 v = tens ? gt[r * 48 + k] : gp[r * 48 + k];
            s4[r * (ROW_STRIDE / 4) + tens * (TEN_STRIDE / 4) + k] = v;
        }
    }
    __syncthreads();

    const int r = threadIdx.x / 20;      // local row
    const int i = threadIdx.x - r * 20;  // sample index
    const float* sp = sh + r * ROW_STRIDE;
    const float* st = sp + TEN_STRIDE;

    float pxv, pyv, tx, ty;
    eval_spline(sp, i, pxv, pyv);
    eval_spline(st, i, tx, ty);
    float dx = pxv - tx;
    float dy = pyv - ty;
    float acc = dx * dx + dy * dy;

    // warp reduce
#pragma unroll
    for (int o = 16; o > 0; o >>= 1)
        acc += __shfl_down_sync(0xffffffffu, acc, o);
    if ((threadIdx.x & 31) == 0) wsum[threadIdx.x >> 5] = acc;
    __syncthreads();

    if (threadIdx.x == 0) {
        float ssum = 0.0f;
#pragma unroll
        for (int w = 0; w < THREADS / 32; ++w) ssum += wsum[w];
        g_partial[blockIdx.x] = ssum;   // non-atomic: deterministic
    }
}

// Deterministic final reduction: fixed summation order, single block.
__global__ __launch_bounds__(1024)
void bspline_reduce_kernel(float* __restrict__ out) {
    __shared__ float wsum[32];
    const int tid = threadIdx.x;
    float acc = 0.0f;
#pragma unroll
    for (int k = 0; k < NUM_BLOCKS / 1024; ++k)      // 4 strided loads, fixed order
        acc += g_partial[tid + k * 1024];
#pragma unroll
    for (int o = 16; o > 0; o >>= 1)
        acc += __shfl_down_sync(0xffffffffu, acc, o);
    if ((tid & 31) == 0) wsum[tid >> 5] = acc;
    __syncthreads();
    if (tid == 0) {
        float ssum = 0.0f;
#pragma unroll
        for (int w = 0; w < 32; ++w) ssum += wsum[w];
        out[0] = ssum * INV_COUNT;
    }
}

extern "C" void kernel_launch(void* const* d_in, const int* in_sizes, int n_in,
                              void* d_out, int out_size) {
    const float* pred  = (const float*)d_in[0];
    const float* truth = (const float*)d_in[1];
    // d_in[2] (true_masks) ignored: reference rebuilds an all-ones mask.
    float* out = (float*)d_out;
    bspline_loss_kernel<<<NUM_BLOCKS, THREADS>>>(pred, truth);
    bspline_reduce_kernel<<<1, 1024>>>(out);
}